// round 8
// baseline (speedup 1.0000x reference)
#include <cuda_runtime.h>
#include <cstdint>

// Problem constants
#define BATCH    16
#define HW       (1024 * 1024)
#define HW4      (HW / 4)
#define GRIDX    37            // 37*16 = 592 = 148 SMs * 4 CTAs -> one exact wave
#define NT       256
#define NQ       7             // f(alpha*g), lg, omp, tomp, t, bin, bint
#define SMOOTH   1e-6f
#define NBLOCKS  (GRIDX * BATCH)

#define NSLOT    4
#define STRIDE   (GRIDX * NT)                          // 9472 float4s
#define NITER    ((HW4 + STRIDE - 1) / STRIDE)         // 28 (27 full + 1 partial)
#define NFULL    (NITER - 1)                           // 27: always in-bounds

__device__ float        g_part[BATCH * GRIDX * 8];
__device__ unsigned int g_count;   // zero-init; self-resets each launch

typedef unsigned long long ull;

// ---------- f32x2 packed helpers ----------
__device__ __forceinline__ ull pk2(float lo, float hi) {
    ull r; asm("mov.b64 %0, {%1, %2};" : "=l"(r) : "f"(lo), "f"(hi)); return r;
}
__device__ __forceinline__ void upk2(ull v, float& lo, float& hi) {
    asm("mov.b64 {%0, %1}, %2;" : "=f"(lo), "=f"(hi) : "l"(v));
}
__device__ __forceinline__ ull mul2(ull a, ull b) {
    ull r; asm("mul.rn.f32x2 %0, %1, %2;" : "=l"(r) : "l"(a), "l"(b)); return r;
}
__device__ __forceinline__ ull add2(ull a, ull b) {
    ull r; asm("add.rn.f32x2 %0, %1, %2;" : "=l"(r) : "l"(a), "l"(b)); return r;
}
__device__ __forceinline__ ull fma2(ull a, ull b, ull c) {
    ull r; asm("fma.rn.f32x2 %0, %1, %2, %3;" : "=l"(r) : "l"(a), "l"(b), "l"(c)); return r;
}
__device__ __forceinline__ float tanha(float x) {
    float r; asm("tanh.approx.f32 %0, %1;" : "=f"(r) : "f"(x)); return r;
}
__device__ __forceinline__ float lg2a(float x) {
    float r; asm("lg2.approx.f32 %0, %1;" : "=f"(r) : "f"(x)); return r;
}
__device__ __forceinline__ float setgt0(float x) {   // (x > 0) ? 1.0f : 0.0f
    float r; asm("set.gt.f32.f32 %0, %1, 0f00000000;" : "=f"(r) : "f"(x)); return r;
}

// ---------- cp.async (LDGSTS) helpers ----------
__device__ __forceinline__ uint32_t smem_u32(const void* p) {
    uint32_t a;
    asm("{ .reg .u64 t; cvta.to.shared.u64 t, %1; cvt.u32.u64 %0, t; }" : "=r"(a) : "l"(p));
    return a;
}
__device__ __forceinline__ void cp16(uint32_t dst, const void* src) {
    asm volatile("cp.async.cg.shared.global [%0], [%1], 16;"
                 :: "r"(dst), "l"(src) : "memory");
}
__device__ __forceinline__ void cp_commit() {
    asm volatile("cp.async.commit_group;" ::: "memory");
}
__device__ __forceinline__ void cp_wait2() {
    asm volatile("cp.async.wait_group 2;" ::: "memory");
}
__device__ __forceinline__ void cp_wait0() {
    asm volatile("cp.async.wait_group 0;" ::: "memory");
}

struct Accs { ull f, lg, omp, tomp, t, bin, bint; };

// Per-pair math, t in {0,1}:
//   z/2 = (t-0.5)x ; h = tanh(z/2) ; p_t = 0.5 + 0.5h
//   ce  = -ln(p_t) = -ln2 * lg2(p_t)
//   omp = 1 - p_t = 0.5 - 0.5h
//   focal elem = (0.75-0.5t) * ce * omp^2    (-ln2 folded in epilogue)
//   Sp = omp + t - 2*tomp ; Spt = t - tomp   (recovered in epilogue)
__device__ __forceinline__ void group(Accs& A, float x0, float x1, float t0, float t1,
                                      ull HALF2, ull MHALF2, ull K75) {
    ull x2 = pk2(x0, x1);
    ull t2 = pk2(t0, t1);
    ull c2 = add2(t2, MHALF2);           // t - 0.5
    ull z2 = mul2(x2, c2);               // (t-0.5)x
    float z0, z1; upk2(z2, z0, z1);
    float h0 = tanha(z0), h1 = tanha(z1);    // MUFU x2
    ull h2 = pk2(h0, h1);
    ull pt2 = fma2(h2, HALF2, HALF2);    // p_t
    float q0, q1; upk2(pt2, q0, q1);
    float l0 = lg2a(q0), l1 = lg2a(q1);      // MUFU x2
    ull l2 = pk2(l0, l1);                // lg2(p_t)  (negative of ce/ln2)
    ull omp2 = fma2(h2, MHALF2, HALF2);  // 1 - p_t
    ull o2   = mul2(omp2, omp2);
    ull g2   = mul2(l2, o2);             // lg2(p_t)*omp^2
    ull a2   = fma2(t2, MHALF2, K75);    // 0.75 - 0.5t
    A.f    = fma2(a2, g2, A.f);
    A.lg   = add2(A.lg, l2);
    A.omp  = add2(A.omp, omp2);
    A.tomp = fma2(t2, omp2, A.tomp);
    A.t    = add2(A.t, t2);
    ull bin2 = pk2(setgt0(x0), setgt0(x1));
    A.bin  = add2(A.bin, bin2);
    A.bint = fma2(t2, bin2, A.bint);
}

__device__ __forceinline__ float warp_sum(float v) {
    #pragma unroll
    for (int off = 16; off > 0; off >>= 1)
        v += __shfl_xor_sync(0xFFFFFFFFu, v, off);
    return v;
}

__global__ __launch_bounds__(NT, 4)
void loss_fused_kernel(const float4* __restrict__ pred,
                       const float4* __restrict__ gt,
                       const float*  __restrict__ pred_iou,
                       float*        __restrict__ out) {
    // Per-thread private staging: [slot][tid] 16B each -> 32 KB total
    __shared__ float4 st_p[NSLOT][NT];
    __shared__ float4 st_g[NSLOT][NT];

    const int tid = threadIdx.x;
    const int img = blockIdx.y;

    const float4* pimg = pred + (size_t)img * HW4;
    const float4* gimg = gt   + (size_t)img * HW4;

    const uint32_t spb = smem_u32(&st_p[0][tid]);   // + slot*4096
    const uint32_t sgb = smem_u32(&st_g[0][tid]);

    const int base = blockIdx.x * NT + tid;

    // prologue: stage slots 0..2 (all in-bounds: base + 2*STRIDE < HW4)
    #pragma unroll
    for (int j = 0; j < NSLOT - 1; j++) {
        cp16(spb + (uint32_t)j * (NT * 16), pimg + base + j * STRIDE);
        cp16(sgb + (uint32_t)j * (NT * 16), gimg + base + j * STRIDE);
        cp_commit();
    }

    const ull HALF2  = pk2(0.5f, 0.5f);
    const ull MHALF2 = pk2(-0.5f, -0.5f);
    const ull K75    = pk2(0.75f, 0.75f);

    Accs A;
    A.f = A.lg = A.omp = A.tomp = A.t = A.bin = A.bint = pk2(0.0f, 0.0f);

    // 27 full iterations, no bounds checks on consume
    for (int j = 0; j < NFULL; j++) {
        cp_wait2();
        const int slot = j & (NSLOT - 1);
        float4 p4 = st_p[slot][tid];
        float4 g4 = st_g[slot][tid];

        const int idxn = base + (j + NSLOT - 1) * STRIDE;
        if (idxn < HW4) {
            const uint32_t soff = (uint32_t)((j + NSLOT - 1) & (NSLOT - 1)) * (NT * 16);
            cp16(spb + soff, pimg + idxn);
            cp16(sgb + soff, gimg + idxn);
        }
        cp_commit();

        group(A, p4.x, p4.y, g4.x, g4.y, HALF2, MHALF2, K75);
        group(A, p4.z, p4.w, g4.z, g4.w, HALF2, MHALF2, K75);
    }
    // tail: iteration 27, partial
    cp_wait0();
    if (base + NFULL * STRIDE < HW4) {
        const int slot = NFULL & (NSLOT - 1);
        float4 p4 = st_p[slot][tid];
        float4 g4 = st_g[slot][tid];
        group(A, p4.x, p4.y, g4.x, g4.y, HALF2, MHALF2, K75);
        group(A, p4.z, p4.w, g4.z, g4.w, HALF2, MHALF2, K75);
    }

    // collapse packed halves
    float vals[NQ];
    {
        float lo, hi;
        upk2(A.f,    lo, hi); vals[0] = lo + hi;
        upk2(A.lg,   lo, hi); vals[1] = lo + hi;
        upk2(A.omp,  lo, hi); vals[2] = lo + hi;
        upk2(A.tomp, lo, hi); vals[3] = lo + hi;
        upk2(A.t,    lo, hi); vals[4] = lo + hi;
        upk2(A.bin,  lo, hi); vals[5] = lo + hi;
        upk2(A.bint, lo, hi); vals[6] = lo + hi;
    }

    // -------- block reduction --------
    #pragma unroll
    for (int q = 0; q < NQ; q++) vals[q] = warp_sum(vals[q]);

    __shared__ float sm[NT / 32][NQ];
    const int lane = tid & 31;
    const int warp = tid >> 5;
    if (lane == 0) {
        #pragma unroll
        for (int q = 0; q < NQ; q++) sm[warp][q] = vals[q];
    }
    __syncthreads();

    __shared__ bool is_last;
    if (warp == 0) {
        #pragma unroll
        for (int q = 0; q < NQ; q++) {
            float v = (lane < NT / 32) ? sm[lane][q] : 0.0f;
            v = warp_sum(v);
            if (lane == 0) vals[q] = v;
        }
        if (lane == 0) {
            float* dst = g_part + ((size_t)img * GRIDX + blockIdx.x) * 8;
            #pragma unroll
            for (int q = 0; q < NQ; q++) dst[q] = vals[q];
            __threadfence();
            unsigned int v = atomicAdd(&g_count, 1u);
            is_last = (v == (unsigned int)(NBLOCKS - 1));
        }
    }
    __syncthreads();
    if (!is_last) return;

    // -------- epilogue: last block reduces 592 partials --------
    __shared__ float agg[BATCH][4];
    for (int b = warp; b < BATCH; b += NT / 32) {
        float s[NQ] = {0.f, 0.f, 0.f, 0.f, 0.f, 0.f, 0.f};
        for (int j = lane; j < GRIDX; j += 32) {
            const float* q = g_part + ((size_t)b * GRIDX + j) * 8;
            #pragma unroll
            for (int k = 0; k < NQ; k++) s[k] += q[k];
        }
        #pragma unroll
        for (int k = 0; k < NQ; k++) s[k] = warp_sum(s[k]);
        if (lane == 0) {
            // s: 0=f(alpha*lg2pt*omp^2) 1=lg 2=omp 3=tomp 4=t 5=bin 6=bint
            float Sp  = s[2] + s[4] - 2.0f * s[3];   // sum p
            float Spt = s[4] - s[3];                 // sum p*t
            float dice_term = (2.0f * Spt + SMOOTH) / (Sp + s[4] + SMOOTH);
            float inter  = s[6];
            float uni    = s[5] + s[4] - s[6];
            float actual = (inter + SMOOTH) / (uni + SMOOTH);
            float d = pred_iou[b] - actual;
            agg[b][0] = s[0];          // x (-ln2) later
            agg[b][1] = s[1];          // x (-ln2) later -> sum ce
            agg[b][2] = dice_term;
            agg[b][3] = d * d;
        }
    }
    __syncthreads();

    if (tid == 0) {
        float fsum = 0.f, csum = 0.f, dsum = 0.f, isum = 0.f;
        #pragma unroll
        for (int b = 0; b < BATCH; b++) {
            fsum += agg[b][0];
            csum += agg[b][1];
            dsum += agg[b][2];
            isum += agg[b][3];
        }
        const float NLN2 = -0.6931471805599453f;
        const float invN = 1.0f / (float)((long long)BATCH * HW);
        float focal    = NLN2 * fsum * invN;
        float dice     = 1.0f - dsum / (float)BATCH;
        float boundary = NLN2 * csum * invN;   // mean(ce) = 0.5 * (2*mean(ce))
        float iou_loss = 0.1f * (isum / (float)BATCH);
        out[0] = focal + dice + boundary + iou_loss;
        g_count = 0;   // reset for next graph replay
    }
}

extern "C" void kernel_launch(void* const* d_in, const int* in_sizes, int n_in,
                              void* d_out, int out_size) {
    const float4* pred = (const float4*)d_in[0];
    const float4* gt   = (const float4*)d_in[1];
    const float*  piou = (const float*)d_in[2];
    float* out = (float*)d_out;

    dim3 grid(GRIDX, BATCH);
    loss_fused_kernel<<<grid, NT>>>(pred, gt, piou, out);
}

// round 9
// speedup vs baseline: 1.0066x; 1.0066x over previous
#include <cuda_runtime.h>
#include <cstdint>

// Problem constants
#define BATCH    16
#define HW       (1024 * 1024)
#define HW4      (HW / 4)
#define GRIDX    37            // 37*16 = 592 = 148 SMs * 4 CTAs -> one exact wave
#define NT       384           // 12 warps/CTA * 4 CTAs = 48 warps/SM
#define NWARP    (NT / 32)
#define NQ       7             // f(alpha*g), lg, omp, tomp, t, bin, bint
#define SMOOTH   1e-6f
#define NBLOCKS  (GRIDX * BATCH)

#define NSLOT    3
#define STRIDE   (GRIDX * NT)                          // 14208 float4s
#define NFULL    18                                    // j=0..17 always in-bounds
// max idx at j=17: 14207 + 17*14208 = 255743 < 262144 (ok); j=18 guarded.

__device__ float        g_part[BATCH * GRIDX * 8];
__device__ unsigned int g_count;   // zero-init; self-resets each launch

typedef unsigned long long ull;

// ---------- f32x2 packed helpers ----------
__device__ __forceinline__ ull pk2(float lo, float hi) {
    ull r; asm("mov.b64 %0, {%1, %2};" : "=l"(r) : "f"(lo), "f"(hi)); return r;
}
__device__ __forceinline__ void upk2(ull v, float& lo, float& hi) {
    asm("mov.b64 {%0, %1}, %2;" : "=f"(lo), "=f"(hi) : "l"(v));
}
__device__ __forceinline__ ull mul2(ull a, ull b) {
    ull r; asm("mul.rn.f32x2 %0, %1, %2;" : "=l"(r) : "l"(a), "l"(b)); return r;
}
__device__ __forceinline__ ull add2(ull a, ull b) {
    ull r; asm("add.rn.f32x2 %0, %1, %2;" : "=l"(r) : "l"(a), "l"(b)); return r;
}
__device__ __forceinline__ ull fma2(ull a, ull b, ull c) {
    ull r; asm("fma.rn.f32x2 %0, %1, %2, %3;" : "=l"(r) : "l"(a), "l"(b), "l"(c)); return r;
}
__device__ __forceinline__ float tanha(float x) {
    float r; asm("tanh.approx.f32 %0, %1;" : "=f"(r) : "f"(x)); return r;
}
__device__ __forceinline__ float lg2a(float x) {
    float r; asm("lg2.approx.f32 %0, %1;" : "=f"(r) : "f"(x)); return r;
}
__device__ __forceinline__ float setgt0(float x) {
    float r; asm("set.gt.f32.f32 %0, %1, 0f00000000;" : "=f"(r) : "f"(x)); return r;
}

// ---------- cp.async helpers ----------
__device__ __forceinline__ uint32_t smem_u32(const void* p) {
    uint32_t a;
    asm("{ .reg .u64 t; cvta.to.shared.u64 t, %1; cvt.u32.u64 %0, t; }" : "=r"(a) : "l"(p));
    return a;
}
__device__ __forceinline__ void cp16(uint32_t dst, const void* src) {
    asm volatile("cp.async.cg.shared.global [%0], [%1], 16;"
                 :: "r"(dst), "l"(src) : "memory");
}
__device__ __forceinline__ void cp_commit() {
    asm volatile("cp.async.commit_group;" ::: "memory");
}
__device__ __forceinline__ void cp_wait1() {
    asm volatile("cp.async.wait_group 1;" ::: "memory");
}
__device__ __forceinline__ void cp_wait0() {
    asm volatile("cp.async.wait_group 0;" ::: "memory");
}

struct Accs { ull f, lg, omp, tomp, t, bin, bint; };

// Per-pair math, t in {0,1}:
//   h = tanh((t-0.5)x) ; p_t = 0.5+0.5h ; ce = -ln2*lg2(p_t) ; omp = 0.5-0.5h
//   focal elem = (0.75-0.5t)*lg2(p_t)*omp^2       (-ln2 folded in epilogue)
//   Sp = omp + t - 2*tomp ; Spt = t - tomp         (recovered in epilogue)
__device__ __forceinline__ void group(Accs& A, float x0, float x1, float t0, float t1,
                                      ull HALF2, ull MHALF2, ull K75) {
    ull x2 = pk2(x0, x1);
    ull t2 = pk2(t0, t1);
    ull c2 = add2(t2, MHALF2);           // t - 0.5
    ull z2 = mul2(x2, c2);
    float z0, z1; upk2(z2, z0, z1);
    float h0 = tanha(z0), h1 = tanha(z1);
    ull h2 = pk2(h0, h1);
    ull pt2 = fma2(h2, HALF2, HALF2);
    float q0, q1; upk2(pt2, q0, q1);
    float l0 = lg2a(q0), l1 = lg2a(q1);
    ull l2 = pk2(l0, l1);
    ull omp2 = fma2(h2, MHALF2, HALF2);
    ull o2   = mul2(omp2, omp2);
    ull g2   = mul2(l2, o2);
    ull a2   = fma2(t2, MHALF2, K75);
    A.f    = fma2(a2, g2, A.f);
    A.lg   = add2(A.lg, l2);
    A.omp  = add2(A.omp, omp2);
    A.tomp = fma2(t2, omp2, A.tomp);
    A.t    = add2(A.t, t2);
    ull bin2 = pk2(setgt0(x0), setgt0(x1));
    A.bin  = add2(A.bin, bin2);
    A.bint = fma2(t2, bin2, A.bint);
}

__device__ __forceinline__ float warp_sum(float v) {
    #pragma unroll
    for (int off = 16; off > 0; off >>= 1)
        v += __shfl_xor_sync(0xFFFFFFFFu, v, off);
    return v;
}

__global__ __launch_bounds__(NT, 4)   // 1536 thr/SM -> 42-reg budget, 48 warps/SM
void loss_fused_kernel(const float4* __restrict__ pred,
                       const float4* __restrict__ gt,
                       const float*  __restrict__ pred_iou,
                       float*        __restrict__ out) {
    // Per-thread staging: 3 slots x 384 thr x 16 B x 2 arrays = 36 KB/CTA
    __shared__ float4 st_p[NSLOT][NT];
    __shared__ float4 st_g[NSLOT][NT];

    const int tid = threadIdx.x;
    const int img = blockIdx.y;

    const float4* pimg = pred + (size_t)img * HW4;
    const float4* gimg = gt   + (size_t)img * HW4;

    const uint32_t spb = smem_u32(&st_p[0][tid]);   // + slot*(NT*16)
    const uint32_t sgb = smem_u32(&st_g[0][tid]);

    const int base = blockIdx.x * NT + tid;

    // prologue: stage slots 0,1 (always in-bounds)
    #pragma unroll
    for (int j = 0; j < NSLOT - 1; j++) {
        cp16(spb + (uint32_t)j * (NT * 16), pimg + base + j * STRIDE);
        cp16(sgb + (uint32_t)j * (NT * 16), gimg + base + j * STRIDE);
        cp_commit();
    }

    const ull HALF2  = pk2(0.5f, 0.5f);
    const ull MHALF2 = pk2(-0.5f, -0.5f);
    const ull K75    = pk2(0.75f, 0.75f);

    Accs A;
    A.f = A.lg = A.omp = A.tomp = A.t = A.bin = A.bint = pk2(0.0f, 0.0f);

    int slot = 0, slot2 = 2;   // consume slot, prefetch slot (j+2)
    for (int j = 0; j < NFULL; j++) {
        cp_wait1();            // slot j's group complete (<=1 outstanding)
        float4 p4 = st_p[slot][tid];
        float4 g4 = st_g[slot][tid];

        const int idxn = base + (j + 2) * STRIDE;
        if (idxn < HW4) {
            const uint32_t soff = (uint32_t)slot2 * (NT * 16);
            cp16(spb + soff, pimg + idxn);
            cp16(sgb + soff, gimg + idxn);
        }
        cp_commit();
        if (++slot  == NSLOT) slot  = 0;
        if (++slot2 == NSLOT) slot2 = 0;

        group(A, p4.x, p4.y, g4.x, g4.y, HALF2, MHALF2, K75);
        group(A, p4.z, p4.w, g4.z, g4.w, HALF2, MHALF2, K75);
    }
    // tail: iteration 18 (only threads with base < HW4 - 18*STRIDE)
    cp_wait0();
    if (base + NFULL * STRIDE < HW4) {
        float4 p4 = st_p[slot][tid];
        float4 g4 = st_g[slot][tid];
        group(A, p4.x, p4.y, g4.x, g4.y, HALF2, MHALF2, K75);
        group(A, p4.z, p4.w, g4.z, g4.w, HALF2, MHALF2, K75);
    }

    // collapse packed halves
    float vals[NQ];
    {
        float lo, hi;
        upk2(A.f,    lo, hi); vals[0] = lo + hi;
        upk2(A.lg,   lo, hi); vals[1] = lo + hi;
        upk2(A.omp,  lo, hi); vals[2] = lo + hi;
        upk2(A.tomp, lo, hi); vals[3] = lo + hi;
        upk2(A.t,    lo, hi); vals[4] = lo + hi;
        upk2(A.bin,  lo, hi); vals[5] = lo + hi;
        upk2(A.bint, lo, hi); vals[6] = lo + hi;
    }

    // -------- block reduction --------
    #pragma unroll
    for (int q = 0; q < NQ; q++) vals[q] = warp_sum(vals[q]);

    __shared__ float sm[NWARP][NQ];
    const int lane = tid & 31;
    const int warp = tid >> 5;
    if (lane == 0) {
        #pragma unroll
        for (int q = 0; q < NQ; q++) sm[warp][q] = vals[q];
    }
    __syncthreads();

    __shared__ bool is_last;
    if (warp == 0) {
        #pragma unroll
        for (int q = 0; q < NQ; q++) {
            float v = (lane < NWARP) ? sm[lane][q] : 0.0f;
            v = warp_sum(v);
            if (lane == 0) vals[q] = v;
        }
        if (lane == 0) {
            float* dst = g_part + ((size_t)img * GRIDX + blockIdx.x) * 8;
            #pragma unroll
            for (int q = 0; q < NQ; q++) dst[q] = vals[q];
            __threadfence();
            unsigned int v = atomicAdd(&g_count, 1u);
            is_last = (v == (unsigned int)(NBLOCKS - 1));
        }
    }
    __syncthreads();
    if (!is_last) return;

    // -------- epilogue: last block reduces 592 partials --------
    __shared__ float agg[BATCH][4];
    for (int b = warp; b < BATCH; b += NWARP) {
        float s[NQ] = {0.f, 0.f, 0.f, 0.f, 0.f, 0.f, 0.f};
        for (int j = lane; j < GRIDX; j += 32) {
            const float* q = g_part + ((size_t)b * GRIDX + j) * 8;
            #pragma unroll
            for (int k = 0; k < NQ; k++) s[k] += q[k];
        }
        #pragma unroll
        for (int k = 0; k < NQ; k++) s[k] = warp_sum(s[k]);
        if (lane == 0) {
            // s: 0=f 1=lg 2=omp 3=tomp 4=t 5=bin 6=bint
            float Sp  = s[2] + s[4] - 2.0f * s[3];   // sum p
            float Spt = s[4] - s[3];                 // sum p*t
            float dice_term = (2.0f * Spt + SMOOTH) / (Sp + s[4] + SMOOTH);
            float inter  = s[6];
            float uni    = s[5] + s[4] - s[6];
            float actual = (inter + SMOOTH) / (uni + SMOOTH);
            float d = pred_iou[b] - actual;
            agg[b][0] = s[0];
            agg[b][1] = s[1];
            agg[b][2] = dice_term;
            agg[b][3] = d * d;
        }
    }
    __syncthreads();

    if (tid == 0) {
        float fsum = 0.f, csum = 0.f, dsum = 0.f, isum = 0.f;
        #pragma unroll
        for (int b = 0; b < BATCH; b++) {
            fsum += agg[b][0];
            csum += agg[b][1];
            dsum += agg[b][2];
            isum += agg[b][3];
        }
        const float NLN2 = -0.6931471805599453f;
        const float invN = 1.0f / (float)((long long)BATCH * HW);
        float focal    = NLN2 * fsum * invN;
        float dice     = 1.0f - dsum / (float)BATCH;
        float boundary = NLN2 * csum * invN;   // mean(ce) = 0.5*(2*mean(ce))
        float iou_loss = 0.1f * (isum / (float)BATCH);
        out[0] = focal + dice + boundary + iou_loss;
        g_count = 0;   // reset for next graph replay
    }
}

extern "C" void kernel_launch(void* const* d_in, const int* in_sizes, int n_in,
                              void* d_out, int out_size) {
    const float4* pred = (const float4*)d_in[0];
    const float4* gt   = (const float4*)d_in[1];
    const float*  piou = (const float*)d_in[2];
    float* out = (float*)d_out;

    dim3 grid(GRIDX, BATCH);
    loss_fused_kernel<<<grid, NT>>>(pred, gt, piou, out);
}